// round 2
// baseline (speedup 1.0000x reference)
#include <cuda_runtime.h>
#include <cstdint>

// Problem constants
#define MAX_NODES 100000
#define F_DIM     16
#define K_DIM     16
#define OUT_SCALE (1.0f / 128.0f)

// Scratch: Y[n][k*16+o] = sum_i x[n][i] * W[k][i][o]   (102.4 MB)
__device__ float g_Y[(size_t)MAX_NODES * 256];

// ---------- packed fp32x2 helpers (sm_100+ FFMA2) ----------
__device__ __forceinline__ unsigned long long pack2(float a, float b) {
    unsigned long long r;
    asm("mov.b64 %0, {%1, %2};" : "=l"(r) : "f"(a), "f"(b));
    return r;
}
__device__ __forceinline__ void fma2(unsigned long long& d,
                                     unsigned long long a,
                                     unsigned long long b) {
    asm("fma.rn.f32x2 %0, %1, %2, %3;" : "=l"(d) : "l"(a), "l"(b), "l"(d));
}
__device__ __forceinline__ void unpack2(unsigned long long v, float& a, float& b) {
    asm("mov.b64 {%0, %1}, %2;" : "=f"(a), "=f"(b) : "l"(v));
}

// ============================================================================
// Stage 1: Y = X @ W  (per node, all 16 k-blocks)
// lane = node; W reads warp-uniform -> smem broadcast; Y row stores coalesce
// across the k-loop per 16-lane group (64B each).
// ============================================================================
__global__ __launch_bounds__(256)
void stage1_kernel(const float* __restrict__ x,
                   const float* __restrict__ W,
                   int n_nodes) {
    __shared__ float Ws[4096];  // 16 KB: W[k][i][o]
    for (int idx = threadIdx.x; idx < 4096; idx += 256)
        Ws[idx] = W[idx];
    __syncthreads();

    int node = blockIdx.x * 256 + threadIdx.x;
    if (node >= n_nodes) return;

    // Load x row, pre-broadcast each scalar into an f32x2 pair
    unsigned long long x2[16];
    const float4* xp = reinterpret_cast<const float4*>(x + (size_t)node * F_DIM);
#pragma unroll
    for (int q = 0; q < 4; q++) {
        float4 v = xp[q];
        x2[4 * q + 0] = pack2(v.x, v.x);
        x2[4 * q + 1] = pack2(v.y, v.y);
        x2[4 * q + 2] = pack2(v.z, v.z);
        x2[4 * q + 3] = pack2(v.w, v.w);
    }

    float* yrow = g_Y + (size_t)node * 256;

#pragma unroll 1
    for (int k = 0; k < K_DIM; k++) {
        unsigned long long acc0 = 0ull, acc1 = 0ull, acc2 = 0ull, acc3 = 0ull;
        unsigned long long acc4 = 0ull, acc5 = 0ull, acc6 = 0ull, acc7 = 0ull;
        const ulonglong2* wbase =
            reinterpret_cast<const ulonglong2*>(Ws + k * 256);
#pragma unroll
        for (int i = 0; i < F_DIM; i++) {
            ulonglong2 wa = wbase[i * 4 + 0];
            ulonglong2 wb = wbase[i * 4 + 1];
            ulonglong2 wc = wbase[i * 4 + 2];
            ulonglong2 wd = wbase[i * 4 + 3];
            unsigned long long xi = x2[i];
            fma2(acc0, xi, wa.x);
            fma2(acc1, xi, wa.y);
            fma2(acc2, xi, wb.x);
            fma2(acc3, xi, wb.y);
            fma2(acc4, xi, wc.x);
            fma2(acc5, xi, wc.y);
            fma2(acc6, xi, wd.x);
            fma2(acc7, xi, wd.y);
        }
        float o0, o1, o2, o3, o4, o5, o6, o7;
        float o8, o9, oa, ob, oc, od, oe, of_;
        unpack2(acc0, o0, o1); unpack2(acc1, o2, o3);
        unpack2(acc2, o4, o5); unpack2(acc3, o6, o7);
        unpack2(acc4, o8, o9); unpack2(acc5, oa, ob);
        unpack2(acc6, oc, od); unpack2(acc7, oe, of_);
        float4* yo = reinterpret_cast<float4*>(yrow + k * 16);
        yo[0] = make_float4(o0, o1, o2, o3);
        yo[1] = make_float4(o4, o5, o6, o7);
        yo[2] = make_float4(o8, o9, oa, ob);
        yo[3] = make_float4(oc, od, oe, of_);
    }
}

// ============================================================================
// Stage 2: per edge — bilinear combine of 4 Y blocks + vector atomic scatter
// ============================================================================
__global__ __launch_bounds__(256)
void stage2_kernel(const float2* __restrict__ edge_attr,
                   const int* __restrict__ ei,
                   const int* __restrict__ ej,
                   float* __restrict__ out,
                   int n_edges) {
    int e = blockIdx.x * 256 + threadIdx.x;
    if (e >= n_edges) return;

    int di = ei[e];
    int dj = ej[e];
    if (di == dj) return;  // centerIgnore mask

    float2 at = edge_attr[e];
    // hat basis on [-1,1], NB=4: centers -1 + m*(2/3), width 2/3.
    float ux = fminf(fmaxf(at.x, -1.0f), 1.0f);
    float uy = fminf(fmaxf(at.y, -1.0f), 1.0f);
    float vx = (ux + 1.0f) * 1.5f;          // in [0,3]
    float vy = (uy + 1.0f) * 1.5f;
    int a = min((int)vx, 2);
    int b = min((int)vy, 2);
    float s = vx - (float)a;
    float t = vy - (float)b;

    float c00 = (1.0f - s) * (1.0f - t);
    float c01 = (1.0f - s) * t;
    float c10 = s * (1.0f - t);
    float c11 = s * t;

    // k = a*4 + b ; blocks (a,b),(a,b+1) contiguous; (a+1,*) at +64 floats
    const float* ybase = g_Y + (size_t)dj * 256 + (a * 4 + b) * 16;
    const float4* r00 = reinterpret_cast<const float4*>(ybase);
    const float4* r01 = reinterpret_cast<const float4*>(ybase + 16);
    const float4* r10 = reinterpret_cast<const float4*>(ybase + 64);
    const float4* r11 = reinterpret_cast<const float4*>(ybase + 80);

    float* obase = out + (size_t)di * 16;

#pragma unroll
    for (int q = 0; q < 4; q++) {
        float4 y0 = r00[q];
        float4 y1 = r01[q];
        float4 y2 = r10[q];
        float4 y3 = r11[q];
        float m0 = c00 * y0.x + c01 * y1.x + c10 * y2.x + c11 * y3.x;
        float m1 = c00 * y0.y + c01 * y1.y + c10 * y2.y + c11 * y3.y;
        float m2 = c00 * y0.z + c01 * y1.z + c10 * y2.z + c11 * y3.z;
        float m3 = c00 * y0.w + c01 * y1.w + c10 * y2.w + c11 * y3.w;
        m0 *= OUT_SCALE; m1 *= OUT_SCALE; m2 *= OUT_SCALE; m3 *= OUT_SCALE;
        asm volatile("red.global.add.v4.f32 [%0], {%1, %2, %3, %4};"
                     :: "l"(obase + q * 4), "f"(m0), "f"(m1), "f"(m2), "f"(m3)
                     : "memory");
    }
}

extern "C" void kernel_launch(void* const* d_in, const int* in_sizes, int n_in,
                              void* d_out, int out_size) {
    const float*  x  = (const float*)d_in[0];    // [N, 16] f32
    const float2* ea = (const float2*)d_in[1];   // [E, 2]  f32
    const float*  W  = (const float*)d_in[2];    // [16,16,16] f32
    const int*    ei = (const int*)d_in[3];      // [E] int32 (JAX x64 disabled)
    const int*    ej = (const int*)d_in[4];      // [E] int32
    float* out = (float*)d_out;

    int n_nodes = in_sizes[0] / F_DIM;
    int n_edges = in_sizes[1] / 2;

    cudaMemsetAsync(d_out, 0, (size_t)out_size * sizeof(float), 0);

    stage1_kernel<<<(n_nodes + 255) / 256, 256>>>(x, W, n_nodes);
    stage2_kernel<<<(n_edges + 255) / 256, 256>>>(ea, ei, ej, out, n_edges);
}

// round 3
// speedup vs baseline: 1.5306x; 1.5306x over previous
#include <cuda_runtime.h>
#include <cuda_fp16.h>
#include <cstdint>

#define MAX_NODES 100000
#define F_DIM     16
#define K_DIM     16
#define OUT_SCALE (1.0f / 128.0f)

// Scratch: Yh[k][n][16] fp16  (51.2 MB). Layout [k][node][o] so stage1 stores
// coalesce (warp of consecutive nodes writes 1KB contiguous per k).
__device__ __half g_Yh[(size_t)K_DIM * MAX_NODES * 16];

// ---------- packed fp32x2 helpers (sm_100+ FFMA2) ----------
__device__ __forceinline__ unsigned long long pack2(float a, float b) {
    unsigned long long r;
    asm("mov.b64 %0, {%1, %2};" : "=l"(r) : "f"(a), "f"(b));
    return r;
}
__device__ __forceinline__ void fma2(unsigned long long& d,
                                     unsigned long long a,
                                     unsigned long long b) {
    asm("fma.rn.f32x2 %0, %1, %2, %3;" : "=l"(d) : "l"(a), "l"(b), "l"(d));
}
__device__ __forceinline__ void unpack2(unsigned long long v, float& a, float& b) {
    asm("mov.b64 {%0, %1}, %2;" : "=f"(a), "=f"(b) : "l"(v));
}
__device__ __forceinline__ unsigned h2pack(float lo, float hi) {
    __half2 h = __floats2half2_rn(lo, hi);
    return *reinterpret_cast<unsigned*>(&h);
}
__device__ __forceinline__ float2 h2f(unsigned u) {
    __half2 h = *reinterpret_cast<__half2*>(&u);
    return __half22float2(h);
}

// ============================================================================
// Stage 1: Yh[k][n][:] = x[n] @ W[k]   (fp32 math, fp16 store)
// ============================================================================
__global__ __launch_bounds__(256)
void stage1_kernel(const float* __restrict__ x,
                   const float* __restrict__ W,
                   int n_nodes) {
    __shared__ float Ws[4096];  // 16 KB: W[k][i][o]
    for (int idx = threadIdx.x; idx < 4096; idx += 256)
        Ws[idx] = W[idx];
    __syncthreads();

    int node = blockIdx.x * 256 + threadIdx.x;
    if (node >= n_nodes) return;

    unsigned long long x2[16];
    const float4* xp = reinterpret_cast<const float4*>(x + (size_t)node * F_DIM);
#pragma unroll
    for (int q = 0; q < 4; q++) {
        float4 v = xp[q];
        x2[4 * q + 0] = pack2(v.x, v.x);
        x2[4 * q + 1] = pack2(v.y, v.y);
        x2[4 * q + 2] = pack2(v.z, v.z);
        x2[4 * q + 3] = pack2(v.w, v.w);
    }

#pragma unroll 1
    for (int k = 0; k < K_DIM; k++) {
        unsigned long long acc0 = 0ull, acc1 = 0ull, acc2 = 0ull, acc3 = 0ull;
        unsigned long long acc4 = 0ull, acc5 = 0ull, acc6 = 0ull, acc7 = 0ull;
        const ulonglong2* wbase =
            reinterpret_cast<const ulonglong2*>(Ws + k * 256);
#pragma unroll
        for (int i = 0; i < F_DIM; i++) {
            ulonglong2 wa = wbase[i * 4 + 0];
            ulonglong2 wb = wbase[i * 4 + 1];
            ulonglong2 wc = wbase[i * 4 + 2];
            ulonglong2 wd = wbase[i * 4 + 3];
            unsigned long long xi = x2[i];
            fma2(acc0, xi, wa.x);
            fma2(acc1, xi, wa.y);
            fma2(acc2, xi, wb.x);
            fma2(acc3, xi, wb.y);
            fma2(acc4, xi, wc.x);
            fma2(acc5, xi, wc.y);
            fma2(acc6, xi, wd.x);
            fma2(acc7, xi, wd.y);
        }
        float o0, o1, o2, o3, o4, o5, o6, o7;
        float o8, o9, oa, ob, oc, od, oe, of_;
        unpack2(acc0, o0, o1); unpack2(acc1, o2, o3);
        unpack2(acc2, o4, o5); unpack2(acc3, o6, o7);
        unpack2(acc4, o8, o9); unpack2(acc5, oa, ob);
        unpack2(acc6, oc, od); unpack2(acc7, oe, of_);

        uint4 s0, s1;
        s0.x = h2pack(o0, o1); s0.y = h2pack(o2, o3);
        s0.z = h2pack(o4, o5); s0.w = h2pack(o6, o7);
        s1.x = h2pack(o8, o9); s1.y = h2pack(oa, ob);
        s1.z = h2pack(oc, od); s1.w = h2pack(oe, of_);

        // [k][node][16] halfs: 32B per (k,node) -> coalesced 1KB per warp
        uint4* yo = reinterpret_cast<uint4*>(
            g_Yh + ((size_t)k * n_nodes + node) * 16);
        yo[0] = s0;
        yo[1] = s1;
    }
}

// ============================================================================
// Stage 2: per edge — bilinear combine of 4 fp16 Y blocks + atomic scatter
// ============================================================================
__global__ __launch_bounds__(256)
void stage2_kernel(const float2* __restrict__ edge_attr,
                   const int* __restrict__ ei,
                   const int* __restrict__ ej,
                   float* __restrict__ out,
                   int n_nodes, int n_edges) {
    int e = blockIdx.x * 256 + threadIdx.x;
    if (e >= n_edges) return;

    int di = ei[e];
    int dj = ej[e];
    if (di == dj) return;  // centerIgnore

    float2 at = edge_attr[e];
    float ux = fminf(fmaxf(at.x, -1.0f), 1.0f);
    float uy = fminf(fmaxf(at.y, -1.0f), 1.0f);
    float vx = (ux + 1.0f) * 1.5f;
    float vy = (uy + 1.0f) * 1.5f;
    int a = min((int)vx, 2);
    int b = min((int)vy, 2);
    float s = vx - (float)a;
    float t = vy - (float)b;

    float c00 = (1.0f - s) * (1.0f - t) * OUT_SCALE;
    float c01 = (1.0f - s) * t * OUT_SCALE;
    float c10 = s * (1.0f - t) * OUT_SCALE;
    float c11 = s * t * OUT_SCALE;

    int k00 = a * 4 + b;
    size_t row = (size_t)dj * 16;
    size_t kstride = (size_t)n_nodes * 16;
    const uint4* pA = reinterpret_cast<const uint4*>(g_Yh + (size_t)k00 * kstride + row);
    const uint4* pB = reinterpret_cast<const uint4*>(g_Yh + (size_t)(k00 + 1) * kstride + row);
    const uint4* pC = reinterpret_cast<const uint4*>(g_Yh + (size_t)(k00 + 4) * kstride + row);
    const uint4* pD = reinterpret_cast<const uint4*>(g_Yh + (size_t)(k00 + 5) * kstride + row);

    uint4 A0 = pA[0], A1 = pA[1];
    uint4 B0 = pB[0], B1 = pB[1];
    uint4 C0 = pC[0], C1 = pC[1];
    uint4 D0 = pD[0], D1 = pD[1];

    float* obase = out + (size_t)di * 16;

    // segment 0: halfs 0..7 (uint4 comps x,y,z,w = 4 half2)
    {
        float2 fA, fB, fC, fD, m01, m23, m45, m67;
        fA = h2f(A0.x); fB = h2f(B0.x); fC = h2f(C0.x); fD = h2f(D0.x);
        m01.x = c00*fA.x + c01*fB.x + c10*fC.x + c11*fD.x;
        m01.y = c00*fA.y + c01*fB.y + c10*fC.y + c11*fD.y;
        fA = h2f(A0.y); fB = h2f(B0.y); fC = h2f(C0.y); fD = h2f(D0.y);
        m23.x = c00*fA.x + c01*fB.x + c10*fC.x + c11*fD.x;
        m23.y = c00*fA.y + c01*fB.y + c10*fC.y + c11*fD.y;
        fA = h2f(A0.z); fB = h2f(B0.z); fC = h2f(C0.z); fD = h2f(D0.z);
        m45.x = c00*fA.x + c01*fB.x + c10*fC.x + c11*fD.x;
        m45.y = c00*fA.y + c01*fB.y + c10*fC.y + c11*fD.y;
        fA = h2f(A0.w); fB = h2f(B0.w); fC = h2f(C0.w); fD = h2f(D0.w);
        m67.x = c00*fA.x + c01*fB.x + c10*fC.x + c11*fD.x;
        m67.y = c00*fA.y + c01*fB.y + c10*fC.y + c11*fD.y;
        asm volatile("red.global.add.v4.f32 [%0], {%1, %2, %3, %4};"
                     :: "l"(obase + 0), "f"(m01.x), "f"(m01.y), "f"(m23.x), "f"(m23.y)
                     : "memory");
        asm volatile("red.global.add.v4.f32 [%0], {%1, %2, %3, %4};"
                     :: "l"(obase + 4), "f"(m45.x), "f"(m45.y), "f"(m67.x), "f"(m67.y)
                     : "memory");
    }
    // segment 1: halfs 8..15
    {
        float2 fA, fB, fC, fD, m01, m23, m45, m67;
        fA = h2f(A1.x); fB = h2f(B1.x); fC = h2f(C1.x); fD = h2f(D1.x);
        m01.x = c00*fA.x + c01*fB.x + c10*fC.x + c11*fD.x;
        m01.y = c00*fA.y + c01*fB.y + c10*fC.y + c11*fD.y;
        fA = h2f(A1.y); fB = h2f(B1.y); fC = h2f(C1.y); fD = h2f(D1.y);
        m23.x = c00*fA.x + c01*fB.x + c10*fC.x + c11*fD.x;
        m23.y = c00*fA.y + c01*fB.y + c10*fC.y + c11*fD.y;
        fA = h2f(A1.z); fB = h2f(B1.z); fC = h2f(C1.z); fD = h2f(D1.z);
        m45.x = c00*fA.x + c01*fB.x + c10*fC.x + c11*fD.x;
        m45.y = c00*fA.y + c01*fB.y + c10*fC.y + c11*fD.y;
        fA = h2f(A1.w); fB = h2f(B1.w); fC = h2f(C1.w); fD = h2f(D1.w);
        m67.x = c00*fA.x + c01*fB.x + c10*fC.x + c11*fD.x;
        m67.y = c00*fA.y + c01*fB.y + c10*fC.y + c11*fD.y;
        asm volatile("red.global.add.v4.f32 [%0], {%1, %2, %3, %4};"
                     :: "l"(obase + 8), "f"(m01.x), "f"(m01.y), "f"(m23.x), "f"(m23.y)
                     : "memory");
        asm volatile("red.global.add.v4.f32 [%0], {%1, %2, %3, %4};"
                     :: "l"(obase + 12), "f"(m45.x), "f"(m45.y), "f"(m67.x), "f"(m67.y)
                     : "memory");
    }
}

extern "C" void kernel_launch(void* const* d_in, const int* in_sizes, int n_in,
                              void* d_out, int out_size) {
    const float*  x  = (const float*)d_in[0];    // [N, 16] f32
    const float2* ea = (const float2*)d_in[1];   // [E, 2]  f32
    const float*  W  = (const float*)d_in[2];    // [16,16,16] f32
    const int*    ei = (const int*)d_in[3];      // [E] int32
    const int*    ej = (const int*)d_in[4];      // [E] int32
    float* out = (float*)d_out;

    int n_nodes = in_sizes[0] / F_DIM;
    int n_edges = in_sizes[1] / 2;

    cudaMemsetAsync(d_out, 0, (size_t)out_size * sizeof(float), 0);

    stage1_kernel<<<(n_nodes + 255) / 256, 256>>>(x, W, n_nodes);
    stage2_kernel<<<(n_edges + 255) / 256, 256>>>(ea, ei, ej, out, n_nodes, n_edges);
}